// round 12
// baseline (speedup 1.0000x reference)
#include <cuda_runtime.h>
#include <cuda_fp16.h>
#include <cuda_bf16.h>

#define NMAX 100000
#define NPAD (98 * 1024)      // 100352, covers NMAX, int4-aligned chunks
#define EMAX 1600000
#define D 64
#define NCHUNK_MAX 98
#define TPB 256
#define GRID 296              // 148 SMs x 2 CTAs, guaranteed co-resident

// __device__ scratch (no allocations allowed)
__device__ int    g_deg[NPAD];
__device__ int    g_rowstart[NPAD];
__device__ __half g_xh[(size_t)NMAX * D];
__device__ int    g_ecol[EMAX];
__device__ int    g_rank[EMAX];
__device__ volatile unsigned long long g_scan_pair[NCHUNK_MAX];

// software grid barrier state (zero-initialized; gen increments monotonically
// across graph replays -- deterministic, no reset needed)
__device__ unsigned g_bar_count;
__device__ volatile unsigned g_bar_gen;

__device__ __forceinline__ void grid_sync() {
    __threadfence();                      // make this thread's writes visible
    __syncthreads();                      // whole block arrived + fenced
    if (threadIdx.x == 0) {
        unsigned gen = g_bar_gen;
        if (atomicAdd(&g_bar_count, 1u) == gridDim.x - 1) {
            g_bar_count = 0;
            __threadfence();
            g_bar_gen = gen + 1;          // release
        } else {
            while (g_bar_gen == gen) { }  // spin
        }
    }
    __syncthreads();
    __threadfence();                      // acquire
}

// packed fp32x2 FMA (Blackwell)
__device__ __forceinline__ void fma_f32x2(unsigned long long& d,
                                          unsigned long long a,
                                          unsigned long long b,
                                          unsigned long long c) {
    asm("fma.rn.f32x2 %0, %1, %2, %3;" : "=l"(d) : "l"(a), "l"(b), "l"(c));
}
__device__ __forceinline__ unsigned smem_u32(const void* p) {
    return (unsigned)__cvta_generic_to_shared(p);
}
__device__ __forceinline__ void cp_async16(unsigned s, const void* g) {
    asm volatile("cp.async.cg.shared.global [%0], [%1], 16;" :: "r"(s), "l"(g));
}
__device__ __forceinline__ void cp_commit() { asm volatile("cp.async.commit_group;"); }
template <int N> __device__ __forceinline__ void cp_wait() {
    asm volatile("cp.async.wait_group %0;" :: "n"(N));
}

#define GEMM_ROWS 32
#define RPT 8

// ---------------------------------------------------------------------------
// THE kernel: all six phases, grid barriers between.
// ---------------------------------------------------------------------------
__global__ void __launch_bounds__(TPB, 2) k_fused(const int* __restrict__ ei,
                                                  const float* __restrict__ x,
                                                  const float* __restrict__ W,
                                                  float* __restrict__ out,
                                                  int E, int N) {
    __shared__ float  Ws[D * (D + 1)];
    __shared__ float2 xs[2][GEMM_ROWS][D / 2];
    __shared__ int    sh_wsum[8];
    __shared__ int    sh_base;

    const int tid  = threadIdx.x;
    const int bid  = blockIdx.x;
    const int gid  = bid * TPB + tid;
    const int nthr = gridDim.x * TPB;
    const int lane = tid & 31;
    const int wid  = tid >> 5;

    const int E4 = E >> 2;
    const int4* rp4 = reinterpret_cast<const int4*>(ei);
    const int4* cp4 = reinterpret_cast<const int4*>(ei + E);
    const int nchunk = (N + 1023) >> 10;

    // ---- P0: zero padded degree + scan state --------------------------------
    for (int i = gid; i < NPAD; i += nthr) g_deg[i] = 0;
    if (gid < NCHUNK_MAX) g_scan_pair[gid] = 0ULL;
    grid_sync();

    // ---- P1: degree histogram + per-edge rank -------------------------------
    {
        int4* rk4 = reinterpret_cast<int4*>(g_rank);
        for (int q = gid; q < E4; q += nthr) {
            int4 r = __ldg(rp4 + q);
            int4 k;
            k.x = atomicAdd(&g_deg[r.x], 1);
            k.y = atomicAdd(&g_deg[r.y], 1);
            k.z = atomicAdd(&g_deg[r.z], 1);
            k.w = atomicAdd(&g_deg[r.w], 1);
            rk4[q] = k;
        }
        for (int e = (E4 << 2) + gid; e < E; e += nthr)
            g_rank[e] = atomicAdd(&g_deg[__ldg(ei + e)], 1);
    }
    grid_sync();

    // ---- P2: scan (chunks of 1024, 4 items/thread, decoupled lookback) ------
    if (bid < nchunk) {
        int base = (bid << 10) + (tid << 2);
        int4 d = *reinterpret_cast<const int4*>(&g_deg[base]);  // padded, safe
        int s1 = d.x + d.y;
        int s2 = s1 + d.z;
        int tsum = s2 + d.w;

        int inc = tsum;
#pragma unroll
        for (int off = 1; off < 32; off <<= 1) {
            int t = __shfl_up_sync(0xffffffffu, inc, off);
            if (lane >= off) inc += t;
        }
        if (lane == 31) sh_wsum[wid] = inc;
        __syncthreads();
        if (wid == 0) {
            int v8 = (lane < 8) ? sh_wsum[lane] : 0;
#pragma unroll
            for (int off = 1; off < 8; off <<= 1) {
                int t = __shfl_up_sync(0xffffffffu, v8, off);
                if (lane >= off) v8 += t;
            }
            if (lane < 8) sh_wsum[lane] = v8;   // inclusive warp sums
        }
        __syncthreads();
        int texcl = inc - tsum + ((wid > 0) ? sh_wsum[wid - 1] : 0);
        int block_total = sh_wsum[7];

        if (wid == 0) {
            if (bid == 0) {
                if (lane == 0) {
                    g_scan_pair[0] = (2ULL << 32) | (unsigned)block_total;
                    sh_base = 0;
                }
            } else {
                if (lane == 0)
                    g_scan_pair[bid] = (1ULL << 32) | (unsigned)block_total;
                __syncwarp();
                int bacc = 0;
                int wstart = bid - 1;
                while (true) {
                    int j = wstart - lane;
                    unsigned flag = 0, val = 0;
                    if (j >= 0) {
                        unsigned long long p;
                        do { p = g_scan_pair[j]; } while ((p >> 32) == 0ULL);
                        flag = (unsigned)(p >> 32);
                        val = (unsigned)p;
                    }
                    unsigned b2 = __ballot_sync(0xffffffffu, flag == 2u);
                    if (b2) {
                        int lp = __ffs(b2) - 1;
                        unsigned contrib = (lane <= lp) ? val : 0u;
                        bacc += (int)__reduce_add_sync(0xffffffffu, contrib);
                        break;
                    } else {
                        bacc += (int)__reduce_add_sync(0xffffffffu, val);
                        wstart -= 32;
                    }
                }
                if (lane == 0) {
                    g_scan_pair[bid] = (2ULL << 32) | (unsigned)(bacc + block_total);
                    sh_base = bacc;
                }
            }
        }
        __syncthreads();

        int S = sh_base + texcl;
        int4 o;
        o.x = S;
        o.y = S + d.x;
        o.z = S + s1;
        o.w = S + s2;
        *reinterpret_cast<int4*>(&g_rowstart[base]) = o;
    }
    grid_sync();

    // ---- P3: CSR fill (no atomics) ------------------------------------------
    {
        const int4* rk4 = reinterpret_cast<const int4*>(g_rank);
        for (int q = gid; q < E4; q += nthr) {
            int4 r = __ldg(rp4 + q);
            int4 c = __ldg(cp4 + q);
            int4 k = rk4[q];
            g_ecol[g_rowstart[r.x] + k.x] = c.x;
            g_ecol[g_rowstart[r.y] + k.y] = c.y;
            g_ecol[g_rowstart[r.z] + k.z] = c.z;
            g_ecol[g_rowstart[r.w] + k.w] = c.w;
        }
        for (int e = (E4 << 2) + gid; e < E; e += nthr) {
            int r = __ldg(ei + e);
            g_ecol[g_rowstart[r] + g_rank[e]] = __ldg(ei + E + e);
        }
    }
    // no barrier needed before gemm (gemm reads only g_deg, stable since P1
    // barrier) -- but gather needs BOTH fill and gemm; single barrier after gemm.

    // ---- P4: GEMM xh_h[r] = fp16(rsqrt(deg[r]) * (x[r] @ W^T)) --------------
    {
        const int tx = tid & 63;
        const int ty = tid >> 6;

        for (int i = tid; i < D * D; i += TPB)
            Ws[(i >> 6) * (D + 1) + (i & 63)] = W[i];
        __syncthreads();

        unsigned long long w2[D / 2];
#pragma unroll
        for (int k2 = 0; k2 < D / 2; k2++) {
            float2 p = make_float2(Ws[tx * (D + 1) + 2 * k2],
                                   Ws[tx * (D + 1) + 2 * k2 + 1]);
            w2[k2] = *reinterpret_cast<unsigned long long*>(&p);
        }
        __syncthreads();

        int ntiles = (N + GEMM_ROWS - 1) / GEMM_ROWS;

        auto issue = [&](int t, int buf) {
            const float4* src = reinterpret_cast<const float4*>(x + (size_t)t * GEMM_ROWS * D);
            int limit = (N - t * GEMM_ROWS) * (D / 4);
            unsigned sbase = smem_u32(&xs[buf][0][0]);
#pragma unroll
            for (int rnd = 0; rnd < 2; rnd++) {
                int v = tid + rnd * TPB;
                if (v < 512 && v < limit) cp_async16(sbase + v * 16, src + v);
            }
            cp_commit();
        };

        int t = bid;
        if (t < ntiles) issue(t, 0);
        int buf = 0;

        for (; t < ntiles; t += GRID) {
            int tn = t + GRID;
            bool have_next = (tn < ntiles);
            if (have_next) issue(tn, buf ^ 1);

            if (have_next) cp_wait<1>(); else cp_wait<0>();
            __syncthreads();

            int r0 = ty * RPT;
            unsigned long long acc[RPT];
#pragma unroll
            for (int i = 0; i < RPT; i++) acc[i] = 0ULL;

#pragma unroll
            for (int k2 = 0; k2 < D / 2; k2++) {
                unsigned long long wreg = w2[k2];
#pragma unroll
                for (int i = 0; i < RPT; i++) {
                    float2 xv = xs[buf][r0 + i][k2];
                    unsigned long long xp = *reinterpret_cast<unsigned long long*>(&xv);
                    fma_f32x2(acc[i], xp, wreg, acc[i]);
                }
            }

            int rb = t * GEMM_ROWS;
#pragma unroll
            for (int i = 0; i < RPT; i++) {
                int r = rb + r0 + i;
                if (r < N) {
                    float2 p = *reinterpret_cast<float2*>(&acc[i]);
                    int dg = g_deg[r];
                    float dr = (dg > 0) ? rsqrtf((float)dg) : 0.0f;
                    g_xh[(size_t)r * D + tx] = __float2half_rn(dr * (p.x + p.y));
                }
            }
            __syncthreads();
            buf ^= 1;
        }
    }
    grid_sync();

    // ---- P5: gather, warp per row, x8 edge unroll ---------------------------
    {
        const __half2* xh2 = reinterpret_cast<const __half2*>(g_xh);
        int wi = gid >> 5;
        int nw = nthr >> 5;

        for (int r = wi; r < N; r += nw) {
            int s = g_rowstart[r];
            int dg = g_deg[r];
            int e = s + dg;

            float a0 = 0.f, a1 = 0.f, a2 = 0.f, a3 = 0.f;
            float a4 = 0.f, a5 = 0.f, a6 = 0.f, a7 = 0.f;
            float b0 = 0.f, b1 = 0.f, b2 = 0.f, b3 = 0.f;
            float b4 = 0.f, b5 = 0.f, b6 = 0.f, b7 = 0.f;

            int j = s;
            for (; j + 7 < e; j += 8) {
                int c0 = g_ecol[j];
                int c1 = g_ecol[j + 1];
                int c2 = g_ecol[j + 2];
                int c3 = g_ecol[j + 3];
                int c4 = g_ecol[j + 4];
                int c5 = g_ecol[j + 5];
                int c6 = g_ecol[j + 6];
                int c7 = g_ecol[j + 7];
                float2 f0 = __half22float2(xh2[(size_t)c0 * 32 + lane]);
                float2 f1 = __half22float2(xh2[(size_t)c1 * 32 + lane]);
                float2 f2 = __half22float2(xh2[(size_t)c2 * 32 + lane]);
                float2 f3 = __half22float2(xh2[(size_t)c3 * 32 + lane]);
                float2 f4 = __half22float2(xh2[(size_t)c4 * 32 + lane]);
                float2 f5 = __half22float2(xh2[(size_t)c5 * 32 + lane]);
                float2 f6 = __half22float2(xh2[(size_t)c6 * 32 + lane]);
                float2 f7 = __half22float2(xh2[(size_t)c7 * 32 + lane]);
                a0 += f0.x; b0 += f0.y;
                a1 += f1.x; b1 += f1.y;
                a2 += f2.x; b2 += f2.y;
                a3 += f3.x; b3 += f3.y;
                a4 += f4.x; b4 += f4.y;
                a5 += f5.x; b5 += f5.y;
                a6 += f6.x; b6 += f6.y;
                a7 += f7.x; b7 += f7.y;
            }
            for (; j < e; j++) {
                int c = g_ecol[j];
                float2 f = __half22float2(xh2[(size_t)c * 32 + lane]);
                a0 += f.x; b0 += f.y;
            }

            float dr = (dg > 0) ? rsqrtf((float)dg) : 0.0f;
            float sx = ((a0 + a1) + (a2 + a3)) + ((a4 + a5) + (a6 + a7));
            float sy = ((b0 + b1) + (b2 + b3)) + ((b4 + b5) + (b6 + b7));
            float2 res = make_float2(dr * sx, dr * sy);
            reinterpret_cast<float2*>(out)[(size_t)r * 32 + lane] = res;
        }
    }
}

// ---------------------------------------------------------------------------
// launch: ONE kernel
// ---------------------------------------------------------------------------
extern "C" void kernel_launch(void* const* d_in, const int* in_sizes, int n_in,
                              void* d_out, int out_size) {
    const int*   edge_index = (const int*)d_in[0];
    const float* x          = (const float*)d_in[1];
    const float* W          = (const float*)d_in[2];
    float*       out        = (float*)d_out;

    int E = in_sizes[0] / 2;
    int N = in_sizes[1] / D;

    k_fused<<<GRID, TPB>>>(edge_index, x, W, out, E, N);
}

// round 13
// speedup vs baseline: 1.2284x; 1.2284x over previous
#include <cuda_runtime.h>
#include <cuda_fp16.h>
#include <cuda_bf16.h>

#define NMAX 100000
#define NPAD (98 * 1024)      // 100352: covers NMAX, int4-aligned 1024-chunks
#define EMAX 1600000
#define D 64
#define NCHUNK_MAX 98
#define TPB 256
#define GRID_A 888            // 148 SMs x 6 CTAs, co-resident under launch_bounds(256,6)

// __device__ scratch (no allocations allowed)
__device__ int    g_deg[NPAD];
__device__ int    g_rowstart[NPAD];
__device__ __half g_xh[(size_t)NMAX * D];
__device__ int    g_ecol[EMAX];
__device__ int    g_rank[EMAX];
__device__ volatile unsigned long long g_scan_pair[NCHUNK_MAX];

// software grid barrier (gen monotonic across graph replays; count self-resets)
__device__ unsigned g_bar_count;
__device__ volatile unsigned g_bar_gen;

__device__ __forceinline__ void grid_sync() {
    __threadfence();
    __syncthreads();
    if (threadIdx.x == 0) {
        unsigned gen = g_bar_gen;
        if (atomicAdd(&g_bar_count, 1u) == gridDim.x - 1) {
            g_bar_count = 0;
            __threadfence();
            g_bar_gen = gen + 1;
        } else {
            while (g_bar_gen == gen) { }
        }
    }
    __syncthreads();
    __threadfence();
}

// packed fp32x2 FMA (Blackwell)
__device__ __forceinline__ void fma_f32x2(unsigned long long& d,
                                          unsigned long long a,
                                          unsigned long long b,
                                          unsigned long long c) {
    asm("fma.rn.f32x2 %0, %1, %2, %3;" : "=l"(d) : "l"(a), "l"(b), "l"(c));
}
__device__ __forceinline__ unsigned smem_u32(const void* p) {
    return (unsigned)__cvta_generic_to_shared(p);
}
__device__ __forceinline__ void cp_async16(unsigned s, const void* g) {
    asm volatile("cp.async.cg.shared.global [%0], [%1], 16;" :: "r"(s), "l"(g));
}
__device__ __forceinline__ void cp_commit() { asm volatile("cp.async.commit_group;"); }
template <int N> __device__ __forceinline__ void cp_wait() {
    asm volatile("cp.async.wait_group %0;" :: "n"(N));
}

// ---------------------------------------------------------------------------
// Kernel A: CSR build (zero -> degree+rank -> scan -> fill), persistent,
// high-occupancy (low-reg), grid barriers between phases.
// ---------------------------------------------------------------------------
__global__ void __launch_bounds__(TPB, 6) k_build(const int* __restrict__ ei,
                                                  int E, int N) {
    __shared__ int sh_wsum[8];
    __shared__ int sh_base;

    const int tid  = threadIdx.x;
    const int bid  = blockIdx.x;
    const int gid  = bid * TPB + tid;
    const int nthr = gridDim.x * TPB;
    const int lane = tid & 31;
    const int wid  = tid >> 5;

    const int E4 = E >> 2;
    const int4* rp4 = reinterpret_cast<const int4*>(ei);
    const int4* cp4 = reinterpret_cast<const int4*>(ei + E);
    const int nchunk = (N + 1023) >> 10;

    // ---- P0: zero padded degree + scan state
    for (int i = gid; i < NPAD; i += nthr) g_deg[i] = 0;
    if (gid < NCHUNK_MAX) g_scan_pair[gid] = 0ULL;
    grid_sync();

    // ---- P1: degree histogram + per-edge rank
    {
        int4* rk4 = reinterpret_cast<int4*>(g_rank);
        for (int q = gid; q < E4; q += nthr) {
            int4 r = __ldg(rp4 + q);
            int4 k;
            k.x = atomicAdd(&g_deg[r.x], 1);
            k.y = atomicAdd(&g_deg[r.y], 1);
            k.z = atomicAdd(&g_deg[r.z], 1);
            k.w = atomicAdd(&g_deg[r.w], 1);
            rk4[q] = k;
        }
        for (int e = (E4 << 2) + gid; e < E; e += nthr)
            g_rank[e] = atomicAdd(&g_deg[__ldg(ei + e)], 1);
    }
    grid_sync();

    // ---- P2: scan (first nchunk blocks; 1024 items/chunk, 4/thread)
    if (bid < nchunk) {
        int base = (bid << 10) + (tid << 2);
        int4 d = *reinterpret_cast<const int4*>(&g_deg[base]);   // padded, safe
        int s1 = d.x + d.y;
        int s2 = s1 + d.z;
        int tsum = s2 + d.w;

        int inc = tsum;
#pragma unroll
        for (int off = 1; off < 32; off <<= 1) {
            int t = __shfl_up_sync(0xffffffffu, inc, off);
            if (lane >= off) inc += t;
        }
        if (lane == 31) sh_wsum[wid] = inc;
        __syncthreads();
        if (wid == 0) {
            int v8 = (lane < 8) ? sh_wsum[lane] : 0;
#pragma unroll
            for (int off = 1; off < 8; off <<= 1) {
                int t = __shfl_up_sync(0xffffffffu, v8, off);
                if (lane >= off) v8 += t;
            }
            if (lane < 8) sh_wsum[lane] = v8;
        }
        __syncthreads();
        int texcl = inc - tsum + ((wid > 0) ? sh_wsum[wid - 1] : 0);
        int block_total = sh_wsum[7];

        if (wid == 0) {
            if (bid == 0) {
                if (lane == 0) {
                    g_scan_pair[0] = (2ULL << 32) | (unsigned)block_total;
                    sh_base = 0;
                }
            } else {
                if (lane == 0)
                    g_scan_pair[bid] = (1ULL << 32) | (unsigned)block_total;
                __syncwarp();
                int bacc = 0;
                int wstart = bid - 1;
                while (true) {
                    int j = wstart - lane;
                    unsigned flag = 0, val = 0;
                    if (j >= 0) {
                        unsigned long long p;
                        do { p = g_scan_pair[j]; } while ((p >> 32) == 0ULL);
                        flag = (unsigned)(p >> 32);
                        val = (unsigned)p;
                    }
                    unsigned b2 = __ballot_sync(0xffffffffu, flag == 2u);
                    if (b2) {
                        int lp = __ffs(b2) - 1;
                        unsigned contrib = (lane <= lp) ? val : 0u;
                        bacc += (int)__reduce_add_sync(0xffffffffu, contrib);
                        break;
                    } else {
                        bacc += (int)__reduce_add_sync(0xffffffffu, val);
                        wstart -= 32;
                    }
                }
                if (lane == 0) {
                    g_scan_pair[bid] = (2ULL << 32) | (unsigned)(bacc + block_total);
                    sh_base = bacc;
                }
            }
        }
        __syncthreads();

        int S = sh_base + texcl;
        int4 o;
        o.x = S;
        o.y = S + d.x;
        o.z = S + s1;
        o.w = S + s2;
        *reinterpret_cast<int4*>(&g_rowstart[base]) = o;
    }
    grid_sync();

    // ---- P3: CSR fill (no atomics)
    {
        const int4* rk4 = reinterpret_cast<const int4*>(g_rank);
        for (int q = gid; q < E4; q += nthr) {
            int4 r = __ldg(rp4 + q);
            int4 c = __ldg(cp4 + q);
            int4 k = rk4[q];
            g_ecol[g_rowstart[r.x] + k.x] = c.x;
            g_ecol[g_rowstart[r.y] + k.y] = c.y;
            g_ecol[g_rowstart[r.z] + k.z] = c.z;
            g_ecol[g_rowstart[r.w] + k.w] = c.w;
        }
        for (int e = (E4 << 2) + gid; e < E; e += nthr) {
            int r = __ldg(ei + e);
            g_ecol[g_rowstart[r] + g_rank[e]] = __ldg(ei + E + e);
        }
    }
}

// ---------------------------------------------------------------------------
// Kernel B: GEMM xh_h[r] = fp16( rsqrt(deg[r]) * (x[r] @ W^T) )
// Persistent, W register-stationary (f32x2), cp.async double-buffered.
// ---------------------------------------------------------------------------
#define GEMM_ROWS 32
#define RPT 8
#define GEMM_GRID 296

__global__ void __launch_bounds__(256) k_gemm(const float* __restrict__ x,
                                              const float* __restrict__ W, int N) {
    __shared__ float  Ws[D * (D + 1)];
    __shared__ float2 xs[2][GEMM_ROWS][D / 2];

    int tid = threadIdx.x;
    int tx = tid & 63;
    int ty = tid >> 6;

    for (int i = tid; i < D * D; i += 256)
        Ws[(i >> 6) * (D + 1) + (i & 63)] = W[i];
    __syncthreads();

    unsigned long long w2[D / 2];
#pragma unroll
    for (int k2 = 0; k2 < D / 2; k2++) {
        float2 p = make_float2(Ws[tx * (D + 1) + 2 * k2], Ws[tx * (D + 1) + 2 * k2 + 1]);
        w2[k2] = *reinterpret_cast<unsigned long long*>(&p);
    }
    __syncthreads();

    int ntiles = (N + GEMM_ROWS - 1) / GEMM_ROWS;

    auto issue = [&](int t, int buf) {
        const float4* src = reinterpret_cast<const float4*>(x + (size_t)t * GEMM_ROWS * D);
        int limit = (N - t * GEMM_ROWS) * (D / 4);
        unsigned sbase = smem_u32(&xs[buf][0][0]);
#pragma unroll
        for (int rnd = 0; rnd < 2; rnd++) {
            int v = tid + rnd * 256;
            if (v < 512 && v < limit) cp_async16(sbase + v * 16, src + v);
        }
        cp_commit();
    };

    int t = blockIdx.x;
    if (t < ntiles) issue(t, 0);
    int buf = 0;

    for (; t < ntiles; t += GEMM_GRID) {
        int tn = t + GEMM_GRID;
        bool have_next = (tn < ntiles);
        if (have_next) issue(tn, buf ^ 1);

        if (have_next) cp_wait<1>(); else cp_wait<0>();
        __syncthreads();

        int r0 = ty * RPT;
        unsigned long long acc[RPT];
#pragma unroll
        for (int i = 0; i < RPT; i++) acc[i] = 0ULL;

#pragma unroll
        for (int k2 = 0; k2 < D / 2; k2++) {
            unsigned long long wreg = w2[k2];
#pragma unroll
            for (int i = 0; i < RPT; i++) {
                float2 xv = xs[buf][r0 + i][k2];
                unsigned long long xp = *reinterpret_cast<unsigned long long*>(&xv);
                fma_f32x2(acc[i], xp, wreg, acc[i]);
            }
        }

        int rb = t * GEMM_ROWS;
#pragma unroll
        for (int i = 0; i < RPT; i++) {
            int r = rb + r0 + i;
            if (r < N) {
                float2 p = *reinterpret_cast<float2*>(&acc[i]);
                int dg = g_deg[r];
                float dr = (dg > 0) ? rsqrtf((float)dg) : 0.0f;
                g_xh[(size_t)r * D + tx] = __float2half_rn(dr * (p.x + p.y));
            }
        }
        __syncthreads();
        buf ^= 1;
    }
}

// ---------------------------------------------------------------------------
// Kernel C: gather, warp per row, fp16 pre-scaled rows.
// out[r] = rsqrt(deg[r]) * sum_j xh_h[c_j]
// ---------------------------------------------------------------------------
__global__ void k_gather(float* __restrict__ out, int N) {
    int gtid = blockIdx.x * blockDim.x + threadIdx.x;
    int warp = gtid >> 5;
    int lane = threadIdx.x & 31;
    int nwarps = (gridDim.x * blockDim.x) >> 5;

    const __half2* xh2 = reinterpret_cast<const __half2*>(g_xh);

    for (int r = warp; r < N; r += nwarps) {
        int s = g_rowstart[r];
        int dg = g_deg[r];
        int e = s + dg;

        float ax = 0.f, ay = 0.f, bx = 0.f, by = 0.f;
        float cx = 0.f, cy = 0.f, dx = 0.f, dy = 0.f;

        int j = s;
        for (; j + 3 < e; j += 4) {
            int c0 = g_ecol[j];
            int c1 = g_ecol[j + 1];
            int c2 = g_ecol[j + 2];
            int c3 = g_ecol[j + 3];
            float2 f0 = __half22float2(xh2[(size_t)c0 * 32 + lane]);
            float2 f1 = __half22float2(xh2[(size_t)c1 * 32 + lane]);
            float2 f2 = __half22float2(xh2[(size_t)c2 * 32 + lane]);
            float2 f3 = __half22float2(xh2[(size_t)c3 * 32 + lane]);
            ax += f0.x; ay += f0.y;
            bx += f1.x; by += f1.y;
            cx += f2.x; cy += f2.y;
            dx += f3.x; dy += f3.y;
        }
        for (; j < e; j++) {
            int c = g_ecol[j];
            float2 f = __half22float2(xh2[(size_t)c * 32 + lane]);
            ax += f.x; ay += f.y;
        }

        float dr = (dg > 0) ? rsqrtf((float)dg) : 0.0f;
        float2 res = make_float2(dr * (ax + bx + cx + dx),
                                 dr * (ay + by + cy + dy));
        reinterpret_cast<float2*>(out)[(size_t)r * 32 + lane] = res;
    }
}

// ---------------------------------------------------------------------------
// launch: 3 kernels
// ---------------------------------------------------------------------------
extern "C" void kernel_launch(void* const* d_in, const int* in_sizes, int n_in,
                              void* d_out, int out_size) {
    const int*   edge_index = (const int*)d_in[0];
    const float* x          = (const float*)d_in[1];
    const float* W          = (const float*)d_in[2];
    float*       out        = (float*)d_out;

    int E = in_sizes[0] / 2;
    int N = in_sizes[1] / D;

    k_build<<<GRID_A, TPB>>>(edge_index, E, N);
    k_gemm<<<GEMM_GRID, 256>>>(x, W, N);
    k_gather<<<2048, 256>>>(out, N);
}